// round 2
// baseline (speedup 1.0000x reference)
#include <cuda_runtime.h>
#include <cstddef>

#define N_NODES 8192
#define D 128

// Scratch (device globals: no allocation allowed in kernel_launch)
__device__ float g_dinv[N_NODES];
__device__ float g_g[(size_t)N_NODES * D];   // dinv-scaled projected features

// ---------------------------------------------------------------------------
// Kernel 0: row sums of adj -> dinv[i] = rsqrt(deg_i) (0 if deg<=0)
// One block per row, 256 threads, float4 loads, high MLP.
// ---------------------------------------------------------------------------
__global__ void __launch_bounds__(256) rowsum_kernel(const float* __restrict__ adj) {
    int row = blockIdx.x;
    const float4* p = reinterpret_cast<const float4*>(adj + (size_t)row * N_NODES);
    float s = 0.f;
    #pragma unroll 8
    for (int i = threadIdx.x; i < N_NODES / 4; i += 256) {
        float4 v = p[i];
        s += (v.x + v.y) + (v.z + v.w);
    }
    // warp reduce
    #pragma unroll
    for (int o = 16; o > 0; o >>= 1) s += __shfl_down_sync(0xffffffffu, s, o);
    __shared__ float red[8];
    int lane = threadIdx.x & 31, wid = threadIdx.x >> 5;
    if (lane == 0) red[wid] = s;
    __syncthreads();
    if (wid == 0) {
        s = (lane < 8) ? red[lane] : 0.f;
        #pragma unroll
        for (int o = 4; o > 0; o >>= 1) s += __shfl_down_sync(0xffffffffu, s, o);
        if (lane == 0) g_dinv[row] = (s > 0.f) ? rsqrtf(s) : 0.f;
    }
}

// ---------------------------------------------------------------------------
// Kernel 1: g[i,:] = dinv[i] * (x[i,:] @ W)
// Block handles 32 rows; 256 threads: col d = tid%128, row-half = tid/128
// (16 rows each). W streamed from global (L2-resident, 64KB).
// ---------------------------------------------------------------------------
__global__ void __launch_bounds__(256) proj_kernel(const float* __restrict__ x,
                                                   const float* __restrict__ w) {
    __shared__ float xs[32][D];
    int row0 = blockIdx.x * 32;
    int tid = threadIdx.x;
    for (int i = tid; i < 32 * D; i += 256)
        xs[i / D][i % D] = x[(size_t)(row0 + i / D) * D + (i % D)];
    __syncthreads();

    int d = tid & 127;
    int half = tid >> 7;          // 0 or 1
    float acc[16];
    #pragma unroll
    for (int r = 0; r < 16; r++) acc[r] = 0.f;

    for (int k = 0; k < D; k++) {
        float wv = w[k * D + d];
        #pragma unroll
        for (int r = 0; r < 16; r++)
            acc[r] += xs[half * 16 + r][k] * wv;
    }
    #pragma unroll
    for (int r = 0; r < 16; r++) {
        int row = row0 + half * 16 + r;
        g_g[(size_t)row * D + d] = acc[r] * g_dinv[row];
    }
}

// ---------------------------------------------------------------------------
// Kernel 2: out = dinv ⊙ (A @ g) + bias
// C-tile 32x128 per block (grid 256), KC=32. 256 threads laid out as
// ty(8) x tx(32); each thread owns 4 rows x 4 cols (float4 accumulators).
// A-frag reads are warp-broadcast; G-frag reads are conflict-free LDS.128.
// ---------------------------------------------------------------------------
#define TM 32
#define KC 32
__global__ void __launch_bounds__(256) aggregate_kernel(const float* __restrict__ adj,
                                                        const float* __restrict__ bias,
                                                        float* __restrict__ out) {
    __shared__ float  As[TM][KC + 1];
    __shared__ float4 Gs[KC][D / 4];

    int row0 = blockIdx.x * TM;
    int tid = threadIdx.x;
    int tx = tid & 31;   // col group: cols [4*tx, 4*tx+3]
    int ty = tid >> 5;   // row group: rows [4*ty, 4*ty+3]

    float4 acc[4];
    #pragma unroll
    for (int r = 0; r < 4; r++) acc[r] = make_float4(0.f, 0.f, 0.f, 0.f);

    const float4* g4 = reinterpret_cast<const float4*>(g_g);

    for (int k0 = 0; k0 < N_NODES; k0 += KC) {
        // stage A tile (32x32 floats, 4 per thread, coalesced)
        #pragma unroll
        for (int j = 0; j < 4; j++) {
            int idx = tid + j * 256;
            int r = idx >> 5, kk = idx & 31;
            As[r][kk] = adj[(size_t)(row0 + r) * N_NODES + (k0 + kk)];
        }
        // stage G tile (32x128 floats = 32x32 float4, 4 per thread)
        #pragma unroll
        for (int j = 0; j < 4; j++) {
            int idx = tid + j * 256;
            int kk = idx >> 5, dd = idx & 31;
            Gs[kk][dd] = g4[(size_t)(k0 + kk) * (D / 4) + dd];
        }
        __syncthreads();

        #pragma unroll
        for (int kk = 0; kk < KC; kk++) {
            float4 gv = Gs[kk][tx];
            #pragma unroll
            for (int r = 0; r < 4; r++) {
                float a = As[ty * 4 + r][kk];
                acc[r].x = fmaf(a, gv.x, acc[r].x);
                acc[r].y = fmaf(a, gv.y, acc[r].y);
                acc[r].z = fmaf(a, gv.z, acc[r].z);
                acc[r].w = fmaf(a, gv.w, acc[r].w);
            }
        }
        __syncthreads();
    }

    float4 bv = reinterpret_cast<const float4*>(bias)[tx];
    #pragma unroll
    for (int r = 0; r < 4; r++) {
        int row = row0 + ty * 4 + r;
        float di = g_dinv[row];
        float4 o;
        o.x = fmaf(acc[r].x, di, bv.x);
        o.y = fmaf(acc[r].y, di, bv.y);
        o.z = fmaf(acc[r].z, di, bv.z);
        o.w = fmaf(acc[r].w, di, bv.w);
        reinterpret_cast<float4*>(out)[(size_t)row * (D / 4) + tx] = o;
    }
}

// ---------------------------------------------------------------------------
extern "C" void kernel_launch(void* const* d_in, const int* in_sizes, int n_in,
                              void* d_out, int out_size) {
    // Identify inputs by element count (robust to ordering):
    //   adj: 8192*8192, x: 8192*128, weight: 128*128, bias: 128
    const float* x = nullptr;
    const float* adj = nullptr;
    const float* weight = nullptr;
    const float* bias = nullptr;
    for (int i = 0; i < n_in; i++) {
        long long sz = in_sizes[i];
        if (sz == (long long)N_NODES * N_NODES) adj = (const float*)d_in[i];
        else if (sz == (long long)N_NODES * D)  x = (const float*)d_in[i];
        else if (sz == (long long)D * D)        weight = (const float*)d_in[i];
        else if (sz == D)                       bias = (const float*)d_in[i];
    }
    float* out = (float*)d_out;

    rowsum_kernel<<<N_NODES, 256>>>(adj);
    proj_kernel<<<N_NODES / 32, 256>>>(x, weight);
    aggregate_kernel<<<N_NODES / TM, 256>>>(adj, bias, out);
}

// round 4
// speedup vs baseline: 2.9940x; 2.9940x over previous
#include <cuda_runtime.h>
#include <cuda_fp16.h>
#include <cstdint>
#include <cstddef>
#include <cstring>

#define N_NODES 8192
#define D 128
#define KC 64
#define NITER (N_NODES / KC)        // 128
#define MT 64                       // M rows per CTA
#define A_TILE_BYTES (MT * KC * 2)      // 8192
#define B_TILE_BYTES (KC * D * 2)       // 16384
#define STAGE_BYTES (A_TILE_BYTES + B_TILE_BYTES)   // 24576
#define SMEM_BYTES (2 * STAGE_BYTES)                // 49152 (static limit)

// ---------------- device scratch ----------------
__device__ float g_dinv[N_NODES];
__device__ __half g_h[(size_t)N_NODES * D];   // dinv-scaled projected features, fp16 [k][n]

// ---------------- helpers ----------------
__device__ __forceinline__ uint32_t smem_u32(const void* p) {
    uint32_t a;
    asm("{ .reg .u64 t; cvta.to.shared.u64 t, %1; cvt.u32.u64 %0, t; }" : "=r"(a) : "l"(p));
    return a;
}
__device__ __forceinline__ void cp_async16(uint32_t dst, const void* src) {
    asm volatile("cp.async.cg.shared.global [%0], [%1], 16;" :: "r"(dst), "l"(src));
}
__device__ __forceinline__ void cp_commit() {
    asm volatile("cp.async.commit_group;" ::: "memory");
}
__device__ __forceinline__ void cp_wait0() {
    asm volatile("cp.async.wait_group 0;" ::: "memory");
}
__device__ __forceinline__ void ldsm_x4(uint32_t* r, uint32_t a) {
    asm volatile("ldmatrix.sync.aligned.m8n8.x4.shared.b16 {%0,%1,%2,%3}, [%4];"
                 : "=r"(r[0]), "=r"(r[1]), "=r"(r[2]), "=r"(r[3]) : "r"(a));
}
__device__ __forceinline__ void ldsm_x4_t(uint32_t* r, uint32_t a) {
    asm volatile("ldmatrix.sync.aligned.m8n8.x4.trans.shared.b16 {%0,%1,%2,%3}, [%4];"
                 : "=r"(r[0]), "=r"(r[1]), "=r"(r[2]), "=r"(r[3]) : "r"(a));
}
__device__ __forceinline__ void mma16816(float* c, const uint32_t* a, uint32_t b0, uint32_t b1) {
    asm volatile(
        "mma.sync.aligned.m16n8k16.row.col.f32.f16.f16.f32 "
        "{%0,%1,%2,%3},{%4,%5,%6,%7},{%8,%9},{%0,%1,%2,%3};"
        : "+f"(c[0]), "+f"(c[1]), "+f"(c[2]), "+f"(c[3])
        : "r"(a[0]), "r"(a[1]), "r"(a[2]), "r"(a[3]), "r"(b0), "r"(b1));
}
__device__ __forceinline__ void sts128(uint32_t addr, uint4 v) {
    asm volatile("st.shared.v4.u32 [%0], {%1,%2,%3,%4};"
                 :: "r"(addr), "r"(v.x), "r"(v.y), "r"(v.z), "r"(v.w));
}
__device__ __forceinline__ uint32_t h2u(__half2 h) {
    uint32_t u; __builtin_memcpy(&u, &h, 4); return u;
}

// ---------------------------------------------------------------------------
// Kernel 0: rowsum -> dinv  (41us @ 83% DRAM — near roofline, unchanged)
// ---------------------------------------------------------------------------
__global__ void __launch_bounds__(256) rowsum_kernel(const float* __restrict__ adj) {
    int row = blockIdx.x;
    const float4* p = reinterpret_cast<const float4*>(adj + (size_t)row * N_NODES);
    float s = 0.f;
    #pragma unroll 8
    for (int i = threadIdx.x; i < N_NODES / 4; i += 256) {
        float4 v = p[i];
        s += (v.x + v.y) + (v.z + v.w);
    }
    #pragma unroll
    for (int o = 16; o > 0; o >>= 1) s += __shfl_down_sync(0xffffffffu, s, o);
    __shared__ float red[8];
    int lane = threadIdx.x & 31, wid = threadIdx.x >> 5;
    if (lane == 0) red[wid] = s;
    __syncthreads();
    if (wid == 0) {
        s = (lane < 8) ? red[lane] : 0.f;
        #pragma unroll
        for (int o = 4; o > 0; o >>= 1) s += __shfl_down_sync(0xffffffffu, s, o);
        if (lane == 0) g_dinv[row] = (s > 0.f) ? rsqrtf(s) : 0.f;
    }
}

// ---------------------------------------------------------------------------
// Kernel 1: g_h[k][n] = fp16( dinv[k] * (x[k,:] @ W)[n] )
// ---------------------------------------------------------------------------
__global__ void __launch_bounds__(256) proj_kernel(const float* __restrict__ x,
                                                   const float* __restrict__ w) {
    __shared__ float xs[32][D];
    int row0 = blockIdx.x * 32;
    int tid = threadIdx.x;
    for (int i = tid; i < 32 * D; i += 256)
        xs[i / D][i % D] = x[(size_t)(row0 + i / D) * D + (i % D)];
    __syncthreads();

    int d = tid & 127;
    int half_ = tid >> 7;
    float acc[16];
    #pragma unroll
    for (int r = 0; r < 16; r++) acc[r] = 0.f;

    for (int k = 0; k < D; k++) {
        float wv = w[k * D + d];
        #pragma unroll
        for (int r = 0; r < 16; r++)
            acc[r] += xs[half_ * 16 + r][k] * wv;
    }
    #pragma unroll
    for (int r = 0; r < 16; r++) {
        int row = row0 + half_ * 16 + r;
        g_h[(size_t)row * D + d] = __float2half(acc[r] * g_dinv[row]);
    }
}

// ---------------------------------------------------------------------------
// Kernel 2: out = dinv ⊙ (A @ g) + bias via mma.sync fp16 (fp32 accumulate).
// grid 128 CTAs (M=64 each), 256 threads (8 warps: 4 row x 2 col).
// Double-buffered KC=64 stages: A fp32->fp16 via regs, B via cp.async.
// ---------------------------------------------------------------------------
__global__ void __launch_bounds__(256, 1) gemm_kernel(const float* __restrict__ adj,
                                                      const float* __restrict__ bias,
                                                      float* __restrict__ out) {
    __shared__ __align__(16) unsigned char smbuf[SMEM_BYTES];
    const uint32_t sm = smem_u32(smbuf);

    const int tid = threadIdx.x;
    const int lane = tid & 31;
    const int wid = tid >> 5;
    const int wr = wid & 3;          // warp row  (16 rows)
    const int wc = wid >> 2;         // warp col  (64 cols)
    const int row0 = blockIdx.x * MT;

    // ---- loader mapping ----
    const int am = tid >> 2;                 // 0..63  A row within tile
    const int aks = (tid & 3) * 16;          // A k-offset (16 floats)
    const uint32_t axor_st = (uint32_t)(am & 7) << 4;
    const float4* aptr = reinterpret_cast<const float4*>(
        adj + (size_t)(row0 + am) * N_NODES + aks);

    const int bk = tid >> 2;                 // 0..63  B k-row within tile
    const int bnc0 = (tid & 3) * 4;          // 4 chunks of 8 halves
    const uint32_t bxor_st = (uint32_t)(bk & 7) << 4;
    const __half* bptr = g_h + (size_t)bk * D + bnc0 * 8;

    // ---- mma fragment address components (fixed per lane) ----
    const int arow_f = wr * 16 + (lane & 15);          // A frag row
    const uint32_t axor_f = (uint32_t)(arow_f & 7) << 4;
    const int akl8 = (lane >> 4) * 8;                  // A frag k sub-offset
    const int brow_l = (lane & 7) + ((lane >> 3) & 1) * 8;  // B frag k row base
    const uint32_t bxor_f = (uint32_t)(lane & 7) << 4;
    const int bnl8 = (lane >> 4) * 8;                  // B frag n sub-offset
    const int n0w = wc * 64;

    float c[8][4];
    #pragma unroll
    for (int j = 0; j < 8; j++)
        #pragma unroll
        for (int q = 0; q < 4; q++) c[j][q] = 0.f;

    // ---- prologue: prefetch stage 0 ----
    float4 apre[4];
    #pragma unroll
    for (int j = 0; j < 4; j++) apre[j] = aptr[j];
    {
        uint32_t bbase = sm + A_TILE_BYTES;   // stage 0 B
        #pragma unroll
        for (int j = 0; j < 4; j++) {
            uint32_t dst = bbase + ((((uint32_t)bk * D + (bnc0 + j) * 8) * 2) ^ bxor_st);
            cp_async16(dst, bptr + j * 8);
        }
        cp_commit();
    }

    for (int i = 0; i < NITER; i++) {
        const int s = i & 1;
        const uint32_t sA = sm + (uint32_t)s * STAGE_BYTES;
        const uint32_t sB = sA + A_TILE_BYTES;

        // STS A_i (convert fp32 regs -> fp16 tiles)
        {
            uint4 v0, v1;
            v0.x = h2u(__floats2half2_rn(apre[0].x, apre[0].y));
            v0.y = h2u(__floats2half2_rn(apre[0].z, apre[0].w));
            v0.z = h2u(__floats2half2_rn(apre[1].x, apre[1].y));
            v0.w = h2u(__floats2half2_rn(apre[1].z, apre[1].w));
            v1.x = h2u(__floats2half2_rn(apre[2].x, apre[2].y));
            v1.y = h2u(__floats2half2_rn(apre[2].z, apre[2].w));
            v1.z = h2u(__floats2half2_rn(apre[3].x, apre[3].y));
            v1.w = h2u(__floats2half2_rn(apre[3].z, apre[3].w));
            uint32_t a0 = sA + ((((uint32_t)am * KC + aks) * 2) ^ axor_st);
            uint32_t a1 = sA + ((((uint32_t)am * KC + aks + 8) * 2) ^ axor_st);
            sts128(a0, v0);
            sts128(a1, v1);
        }

        cp_wait0();          // B_i resident
        __syncthreads();     // A_i visible; prior compute done

        // prefetch stage i+1 (overlaps compute below)
        if (i + 1 < NITER) {
            const float4* ap = reinterpret_cast<const float4*>(
                adj + (size_t)(row0 + am) * N_NODES + (size_t)(i + 1) * KC + aks);
            #pragma unroll
            for (int j = 0; j < 4; j++) apre[j] = ap[j];
            uint32_t bbase = sm + (uint32_t)(s ^ 1) * STAGE_BYTES + A_TILE_BYTES;
            const __half* bp = bptr + (size_t)(i + 1) * KC * D;
            #pragma unroll
            for (int j = 0; j < 4; j++) {
                uint32_t dst = bbase + ((((uint32_t)bk * D + (bnc0 + j) * 8) * 2) ^ bxor_st);
                cp_async16(dst, bp + j * 8);
            }
            cp_commit();
        }

        // compute stage i: 4 k16 steps
        #pragma unroll
        for (int s16 = 0; s16 < 4; s16++) {
            const int k0 = s16 * 16;
            uint32_t ra[4];
            uint32_t aaddr = sA + ((((uint32_t)arow_f * KC + k0 + akl8) * 2) ^ axor_f);
            ldsm_x4(ra, aaddr);
            #pragma unroll
            for (int nb = 0; nb < 4; nb++) {
                uint32_t rb[4];
                uint32_t baddr = sB +
                    ((((uint32_t)(k0 + brow_l) * D + n0w + nb * 16 + bnl8) * 2) ^ bxor_f);
                ldsm_x4_t(rb, baddr);
                mma16816(c[nb * 2 + 0], ra, rb[0], rb[1]);
                mma16816(c[nb * 2 + 1], ra, rb[2], rb[3]);
            }
        }
    }

    // ---- epilogue: out = c * dinv[row] + bias[col] ----
    const int grp = lane >> 2, tid4 = lane & 3;
    const int r1 = row0 + wr * 16 + grp;
    const int r2 = r1 + 8;
    const float d1 = g_dinv[r1], d2 = g_dinv[r2];
    #pragma unroll
    for (int j = 0; j < 8; j++) {
        int col = n0w + j * 8 + tid4 * 2;
        float b0 = bias[col], b1 = bias[col + 1];
        float2 o1, o2;
        o1.x = fmaf(c[j][0], d1, b0);
        o1.y = fmaf(c[j][1], d1, b1);
        o2.x = fmaf(c[j][2], d2, b0);
        o2.y = fmaf(c[j][3], d2, b1);
        *reinterpret_cast<float2*>(out + (size_t)r1 * D + col) = o1;
        *reinterpret_cast<float2*>(out + (size_t)r2 * D + col) = o2;
    }
}

// ---------------------------------------------------------------------------
extern "C" void kernel_launch(void* const* d_in, const int* in_sizes, int n_in,
                              void* d_out, int out_size) {
    const float* x = nullptr;
    const float* adj = nullptr;
    const float* weight = nullptr;
    const float* bias = nullptr;
    for (int i = 0; i < n_in; i++) {
        long long sz = in_sizes[i];
        if (sz == (long long)N_NODES * N_NODES) adj = (const float*)d_in[i];
        else if (sz == (long long)N_NODES * D)  x = (const float*)d_in[i];
        else if (sz == (long long)D * D)        weight = (const float*)d_in[i];
        else if (sz == D)                       bias = (const float*)d_in[i];
    }
    float* out = (float*)d_out;

    rowsum_kernel<<<N_NODES, 256>>>(adj);
    proj_kernel<<<N_NODES / 32, 256>>>(x, weight);
    gemm_kernel<<<N_NODES / MT, 256>>>(adj, bias, out);
}

// round 5
// speedup vs baseline: 3.1512x; 1.0525x over previous
#include <cuda_runtime.h>
#include <cuda_fp16.h>
#include <cstdint>
#include <cstddef>
#include <cstring>

#define N_NODES 8192
#define D 128
#define KC 128                       // K per stage (two 64-k sub-tiles)
#define NITER (N_NODES / KC)         // 64
#define MT 64                        // M rows per CTA
#define A_SUB_BYTES (MT * 64 * 2)        // 8192
#define B_SUB_BYTES (64 * D * 2)         // 16384
#define STAGE_BYTES (2 * A_SUB_BYTES + 2 * B_SUB_BYTES)   // 49152
#define SMEM_BYTES (2 * STAGE_BYTES)                      // 98304

// ---------------- device scratch ----------------
__device__ float g_dinv[N_NODES];
__device__ __half g_h[(size_t)N_NODES * D];   // dinv-scaled projected features, fp16 [k][n]

// ---------------- helpers ----------------
__device__ __forceinline__ uint32_t smem_u32(const void* p) {
    uint32_t a;
    asm("{ .reg .u64 t; cvta.to.shared.u64 t, %1; cvt.u32.u64 %0, t; }" : "=r"(a) : "l"(p));
    return a;
}
__device__ __forceinline__ void cp_async16(uint32_t dst, const void* src) {
    asm volatile("cp.async.cg.shared.global [%0], [%1], 16;" :: "r"(dst), "l"(src));
}
__device__ __forceinline__ void cp_commit() {
    asm volatile("cp.async.commit_group;" ::: "memory");
}
__device__ __forceinline__ void cp_wait0() {
    asm volatile("cp.async.wait_group 0;" ::: "memory");
}
__device__ __forceinline__ void ldsm_x4(uint32_t* r, uint32_t a) {
    asm volatile("ldmatrix.sync.aligned.m8n8.x4.shared.b16 {%0,%1,%2,%3}, [%4];"
                 : "=r"(r[0]), "=r"(r[1]), "=r"(r[2]), "=r"(r[3]) : "r"(a));
}
__device__ __forceinline__ void ldsm_x4_t(uint32_t* r, uint32_t a) {
    asm volatile("ldmatrix.sync.aligned.m8n8.x4.trans.shared.b16 {%0,%1,%2,%3}, [%4];"
                 : "=r"(r[0]), "=r"(r[1]), "=r"(r[2]), "=r"(r[3]) : "r"(a));
}
__device__ __forceinline__ void mma16816(float* c, const uint32_t* a, uint32_t b0, uint32_t b1) {
    asm volatile(
        "mma.sync.aligned.m16n8k16.row.col.f32.f16.f16.f32 "
        "{%0,%1,%2,%3},{%4,%5,%6,%7},{%8,%9},{%0,%1,%2,%3};"
        : "+f"(c[0]), "+f"(c[1]), "+f"(c[2]), "+f"(c[3])
        : "r"(a[0]), "r"(a[1]), "r"(a[2]), "r"(a[3]), "r"(b0), "r"(b1));
}
__device__ __forceinline__ void sts128(uint32_t addr, uint4 v) {
    asm volatile("st.shared.v4.u32 [%0], {%1,%2,%3,%4};"
                 :: "r"(addr), "r"(v.x), "r"(v.y), "r"(v.z), "r"(v.w));
}
__device__ __forceinline__ uint32_t h2u(__half2 h) {
    uint32_t u; __builtin_memcpy(&u, &h, 4); return u;
}

// ---------------------------------------------------------------------------
// Kernel 0: rowsum -> dinv  (41us @ 83% DRAM — near roofline, unchanged)
// ---------------------------------------------------------------------------
__global__ void __launch_bounds__(256) rowsum_kernel(const float* __restrict__ adj) {
    int row = blockIdx.x;
    const float4* p = reinterpret_cast<const float4*>(adj + (size_t)row * N_NODES);
    float s = 0.f;
    #pragma unroll 8
    for (int i = threadIdx.x; i < N_NODES / 4; i += 256) {
        float4 v = p[i];
        s += (v.x + v.y) + (v.z + v.w);
    }
    #pragma unroll
    for (int o = 16; o > 0; o >>= 1) s += __shfl_down_sync(0xffffffffu, s, o);
    __shared__ float red[8];
    int lane = threadIdx.x & 31, wid = threadIdx.x >> 5;
    if (lane == 0) red[wid] = s;
    __syncthreads();
    if (wid == 0) {
        s = (lane < 8) ? red[lane] : 0.f;
        #pragma unroll
        for (int o = 4; o > 0; o >>= 1) s += __shfl_down_sync(0xffffffffu, s, o);
        if (lane == 0) g_dinv[row] = (s > 0.f) ? rsqrtf(s) : 0.f;
    }
}

// ---------------------------------------------------------------------------
// Kernel 1: g_h[k][n] = fp16( dinv[k] * (x[k,:] @ W)[n] )
// ---------------------------------------------------------------------------
__global__ void __launch_bounds__(256) proj_kernel(const float* __restrict__ x,
                                                   const float* __restrict__ w) {
    __shared__ float xs[32][D];
    int row0 = blockIdx.x * 32;
    int tid = threadIdx.x;
    for (int i = tid; i < 32 * D; i += 256)
        xs[i / D][i % D] = x[(size_t)(row0 + i / D) * D + (i % D)];
    __syncthreads();

    int d = tid & 127;
    int half_ = tid >> 7;
    float acc[16];
    #pragma unroll
    for (int r = 0; r < 16; r++) acc[r] = 0.f;

    for (int k = 0; k < D; k++) {
        float wv = w[k * D + d];
        #pragma unroll
        for (int r = 0; r < 16; r++)
            acc[r] += xs[half_ * 16 + r][k] * wv;
    }
    #pragma unroll
    for (int r = 0; r < 16; r++) {
        int row = row0 + half_ * 16 + r;
        g_h[(size_t)row * D + d] = __float2half(acc[r] * g_dinv[row]);
    }
}

// ---------------------------------------------------------------------------
// Kernel 2: out = dinv ⊙ (A @ g) + bias via mma.sync fp16 (fp32 accumulate).
// grid 128 CTAs (M=64 each), 256 threads (8 warps: 4 row x 2 col).
// KC=128 stages (two 64-k sub-tiles), double-buffered dynamic smem (96KB).
// ---------------------------------------------------------------------------
__global__ void __launch_bounds__(256, 1) gemm_kernel(const float* __restrict__ adj,
                                                      const float* __restrict__ bias,
                                                      float* __restrict__ out) {
    extern __shared__ __align__(16) unsigned char smbuf[];
    const uint32_t sm = smem_u32(smbuf);

    const int tid = threadIdx.x;
    const int lane = tid & 31;
    const int wid = tid >> 5;
    const int wr = wid & 3;          // warp row  (16 rows)
    const int wc = wid >> 2;         // warp col  (64 cols)
    const int row0 = blockIdx.x * MT;

    // ---- loader mapping (per 64-k sub-tile) ----
    const int am = tid >> 2;                 // 0..63  A row within tile
    const int aks = (tid & 3) * 16;          // A k-offset (16 floats)
    const uint32_t axor_st = (uint32_t)(am & 7) << 4;
    const uint32_t a_st_off0 = (((uint32_t)am * 64 + aks) * 2) ^ axor_st;
    const uint32_t a_st_off1 = (((uint32_t)am * 64 + aks + 8) * 2) ^ axor_st;

    const int bk = tid >> 2;                 // 0..63  B k-row within sub-tile
    const int bnc0 = (tid & 3) * 4;          // 4 chunks of 8 halves
    const uint32_t bxor_st = (uint32_t)(bk & 7) << 4;
    uint32_t b_st_off[4];
    #pragma unroll
    for (int j = 0; j < 4; j++)
        b_st_off[j] = (((uint32_t)bk * D + (bnc0 + j) * 8) * 2) ^ bxor_st;
    const __half* bptr = g_h + (size_t)bk * D + bnc0 * 8;

    // ---- mma fragment address components (fixed per lane) ----
    const int arow_f = wr * 16 + (lane & 15);
    const uint32_t axor_f = (uint32_t)(arow_f & 7) << 4;
    const int akl8 = (lane >> 4) * 8;
    const int brow_l = (lane & 7) + ((lane >> 3) & 1) * 8;
    const uint32_t bxor_f = (uint32_t)(lane & 7) << 4;
    const int bnl8 = (lane >> 4) * 8;
    const int n0w = wc * 64;

    float c[8][4];
    #pragma unroll
    for (int j = 0; j < 8; j++)
        #pragma unroll
        for (int q = 0; q < 4; q++) c[j][q] = 0.f;

    const float* arow_ptr = adj + (size_t)(row0 + am) * N_NODES;

    // ---- prologue: prefetch stage 0 (A->regs, B->cp.async) ----
    float4 apre[2][4];
    #pragma unroll
    for (int h = 0; h < 2; h++) {
        const float4* ap = reinterpret_cast<const float4*>(arow_ptr + h * 64 + aks);
        #pragma unroll
        for (int j = 0; j < 4; j++) apre[h][j] = ap[j];
    }
    {
        #pragma unroll
        for (int h = 0; h < 2; h++) {
            uint32_t bbase = sm + 2 * A_SUB_BYTES + (uint32_t)h * B_SUB_BYTES;
            const __half* bp = bptr + (size_t)h * 64 * D;
            #pragma unroll
            for (int j = 0; j < 4; j++)
                cp_async16(bbase + b_st_off[j], bp + j * 8);
        }
        cp_commit();
    }

    for (int i = 0; i < NITER; i++) {
        const int s = i & 1;
        const uint32_t sA = sm + (uint32_t)s * STAGE_BYTES;
        const uint32_t sB = sA + 2 * A_SUB_BYTES;

        // STS A_i (convert fp32 regs -> fp16, both sub-tiles)
        #pragma unroll
        for (int h = 0; h < 2; h++) {
            uint4 v0, v1;
            v0.x = h2u(__floats2half2_rn(apre[h][0].x, apre[h][0].y));
            v0.y = h2u(__floats2half2_rn(apre[h][0].z, apre[h][0].w));
            v0.z = h2u(__floats2half2_rn(apre[h][1].x, apre[h][1].y));
            v0.w = h2u(__floats2half2_rn(apre[h][1].z, apre[h][1].w));
            v1.x = h2u(__floats2half2_rn(apre[h][2].x, apre[h][2].y));
            v1.y = h2u(__floats2half2_rn(apre[h][2].z, apre[h][2].w));
            v1.z = h2u(__floats2half2_rn(apre[h][3].x, apre[h][3].y));
            v1.w = h2u(__floats2half2_rn(apre[h][3].z, apre[h][3].w));
            uint32_t abase = sA + (uint32_t)h * A_SUB_BYTES;
            sts128(abase + a_st_off0, v0);
            sts128(abase + a_st_off1, v1);
        }

        cp_wait0();          // B_i resident
        __syncthreads();     // A_i visible; prior compute done

        // prefetch stage i+1 (overlaps compute below)
        if (i + 1 < NITER) {
            const float* arp = arow_ptr + (size_t)(i + 1) * KC;
            #pragma unroll
            for (int h = 0; h < 2; h++) {
                const float4* ap = reinterpret_cast<const float4*>(arp + h * 64 + aks);
                #pragma unroll
                for (int j = 0; j < 4; j++) apre[h][j] = ap[j];
            }
            uint32_t bstage = sm + (uint32_t)(s ^ 1) * STAGE_BYTES + 2 * A_SUB_BYTES;
            const __half* bp0 = bptr + (size_t)(i + 1) * KC * D;
            #pragma unroll
            for (int h = 0; h < 2; h++) {
                uint32_t bbase = bstage + (uint32_t)h * B_SUB_BYTES;
                const __half* bp = bp0 + (size_t)h * 64 * D;
                #pragma unroll
                for (int j = 0; j < 4; j++)
                    cp_async16(bbase + b_st_off[j], bp + j * 8);
            }
            cp_commit();
        }

        // compute stage i: 2 sub-tiles x 4 k16 steps
        #pragma unroll
        for (int h = 0; h < 2; h++) {
            const uint32_t sAh = sA + (uint32_t)h * A_SUB_BYTES;
            const uint32_t sBh = sB + (uint32_t)h * B_SUB_BYTES;
            #pragma unroll
            for (int s16 = 0; s16 < 4; s16++) {
                const int k0 = s16 * 16;
                uint32_t ra[4];
                uint32_t aaddr = sAh + ((((uint32_t)arow_f * 64 + k0 + akl8) * 2) ^ axor_f);
                ldsm_x4(ra, aaddr);
                #pragma unroll
                for (int nb = 0; nb < 4; nb++) {
                    uint32_t rb[4];
                    uint32_t baddr = sBh +
                        ((((uint32_t)(k0 + brow_l) * D + n0w + nb * 16 + bnl8) * 2) ^ bxor_f);
                    ldsm_x4_t(rb, baddr);
                    mma16816(c[nb * 2 + 0], ra, rb[0], rb[1]);
                    mma16816(c[nb * 2 + 1], ra, rb[2], rb[3]);
                }
            }
        }
    }

    // ---- epilogue: out = c * dinv[row] + bias[col] ----
    const int grp = lane >> 2, tid4 = lane & 3;
    const int r1 = row0 + wr * 16 + grp;
    const int r2 = r1 + 8;
    const float d1 = g_dinv[r1], d2 = g_dinv[r2];
    #pragma unroll
    for (int j = 0; j < 8; j++) {
        int col = n0w + j * 8 + tid4 * 2;
        float b0 = bias[col], b1 = bias[col + 1];
        float2 o1, o2;
        o1.x = fmaf(c[j][0], d1, b0);
        o1.y = fmaf(c[j][1], d1, b1);
        o2.x = fmaf(c[j][2], d2, b0);
        o2.y = fmaf(c[j][3], d2, b1);
        *reinterpret_cast<float2*>(out + (size_t)r1 * D + col) = o1;
        *reinterpret_cast<float2*>(out + (size_t)r2 * D + col) = o2;
    }
}

// ---------------------------------------------------------------------------
extern "C" void kernel_launch(void* const* d_in, const int* in_sizes, int n_in,
                              void* d_out, int out_size) {
    const float* x = nullptr;
    const float* adj = nullptr;
    const float* weight = nullptr;
    const float* bias = nullptr;
    for (int i = 0; i < n_in; i++) {
        long long sz = in_sizes[i];
        if (sz == (long long)N_NODES * N_NODES) adj = (const float*)d_in[i];
        else if (sz == (long long)N_NODES * D)  x = (const float*)d_in[i];
        else if (sz == (long long)D * D)        weight = (const float*)d_in[i];
        else if (sz == D)                       bias = (const float*)d_in[i];
    }
    float* out = (float*)d_out;

    cudaFuncSetAttribute(gemm_kernel,
                         cudaFuncAttributeMaxDynamicSharedMemorySize, SMEM_BYTES);

    rowsum_kernel<<<N_NODES, 256>>>(adj);
    proj_kernel<<<N_NODES / 32, 256>>>(x, weight);
    gemm_kernel<<<N_NODES / MT, 256, SMEM_BYTES>>>(adj, bias, out);
}